// round 5
// baseline (speedup 1.0000x reference)
#include <cuda_runtime.h>
#include <cstdint>

#define RR 100
#define BB 8
#define IWW 64
#define DD 128
#define BDD 32
#define OWW 16
#define TCH 4    // t-tiles per kB CTA

typedef unsigned long long ull;

// ---- packed fp32x2 helpers (sm_103a FFMA2 path, PTX-only) ----
__device__ __forceinline__ ull pk2(float lo, float hi) {
    ull r; asm("mov.b64 %0,{%1,%2};" : "=l"(r) : "f"(lo), "f"(hi)); return r;
}
__device__ __forceinline__ void upk2(float& lo, float& hi, ull v) {
    asm("mov.b64 {%0,%1},%2;" : "=f"(lo), "=f"(hi) : "l"(v));
}
__device__ __forceinline__ ull fma2(ull a, ull b, ull c) {
    ull d; asm("fma.rn.f32x2 %0,%1,%2,%3;" : "=l"(d) : "l"(a), "l"(b), "l"(c)); return d;
}
__device__ __forceinline__ ull add2(ull a, ull b) {
    ull d; asm("add.rn.f32x2 %0,%1,%2;" : "=l"(d) : "l"(a), "l"(b)); return d;
}

// Scratch (allocation-free rule: __device__ globals)
__device__ float g_q[BB * RR * DD];     // [b][r][d]
__device__ float g_K[BB * RR * DD];     // [b][r][d]
__device__ float g_Vn[BB * RR * BDD];   // [b][r][bd]
__device__ float g_attn[BB * RR * RR];  // [b][s][t]  (relu'd raw logits)

// Packed linear stage with 16-deep load batching.
template<int N>
__device__ __forceinline__ void lin2(ull acc2[2], const float* __restrict__ W,
                                     int ldw, const ull x2[][2]) {
    #pragma unroll
    for (int base = 0; base < N; base += 16) {
        float wb[16];
        #pragma unroll
        for (int u = 0; u < 16; u++) wb[u] = __ldg(W + (size_t)(base + u) * ldw);
        #pragma unroll
        for (int u = 0; u < 16; u++) {
            ull w2 = pk2(wb[u], wb[u]);
            acc2[0] = fma2(x2[base + u][0], w2, acc2[0]);
            acc2[1] = fma2(x2[base + u][1], w2, acc2[1]);
        }
    }
}

// ---------------------------------------------------------------------------
// Kernel A: per-region embeddings. grid = (R, 3 paths, 2 batch-halves).
// ---------------------------------------------------------------------------
__global__ __launch_bounds__(128) void kA(
    const float* __restrict__ x, const float* __restrict__ mean,
    const float* __restrict__ stddev,
    const float* __restrict__ kv_in_W, const float* __restrict__ kv_in_b,
    const float* __restrict__ kv_blk_W, const float* __restrict__ kv_blk_b,
    const float* __restrict__ q_in_W, const float* __restrict__ q_in_b,
    const float* __restrict__ q_blk_W, const float* __restrict__ q_blk_b,
    const float* __restrict__ key_W, const float* __restrict__ key_b,
    const float* __restrict__ value_W, const float* __restrict__ value_b)
{
    int r = blockIdx.x;
    int path = blockIdx.y;
    int bh = blockIdx.z;          // batch half: batches [4*bh, 4*bh+4)
    int d = threadIdx.x;

    __shared__ ull xn2[IWW][2];
    __shared__ ull h2[DD][2];
    __shared__ float kvs[4][DD];

    float mu = mean[r];
    float isd = 1.0f / (stddev[r] + 1e-8f);
    {
        int i = d & 63, p = d >> 6;
        int b0 = 4 * bh + 2 * p;
        float a = (x[(b0 * RR + r) * IWW + i] - mu) * isd;
        float bb = (x[((b0 + 1) * RR + r) * IWW + i] - mu) * isd;
        xn2[i][p] = pk2(a, bb);
    }
    __syncthreads();

    ull acc2[2];

    if (path == 0) {
        {
            float bi = q_in_b[r * DD + d];
            acc2[0] = acc2[1] = pk2(bi, bi);
            lin2<IWW>(acc2, q_in_W + (size_t)r * IWW * DD + d, DD, xn2);
            #pragma unroll
            for (int p = 0; p < 2; p++) {
                float lo, hi; upk2(lo, hi, acc2[p]);
                h2[d][p] = pk2(fmaxf(lo, 0.0f), fmaxf(hi, 0.0f));
            }
            __syncthreads();
        }
        {
            float bi = q_blk_b[r * DD + d];
            acc2[0] = acc2[1] = pk2(bi, bi);
            lin2<DD>(acc2, q_blk_W + (size_t)r * DD * DD + d, DD, h2);
            #pragma unroll
            for (int p = 0; p < 2; p++) {
                float lo, hi; upk2(lo, hi, acc2[p]);
                int b0 = 4 * bh + 2 * p;
                g_q[(b0 * RR + r) * DD + d] = lo;
                g_q[((b0 + 1) * RR + r) * DD + d] = hi;
            }
        }
        return;
    }

    {
        float bi = kv_in_b[d];
        acc2[0] = acc2[1] = pk2(bi, bi);
        lin2<IWW>(acc2, kv_in_W + d, DD, xn2);
        #pragma unroll
        for (int p = 0; p < 2; p++) {
            float lo, hi; upk2(lo, hi, acc2[p]);
            h2[d][p] = pk2(fmaxf(lo, 0.0f), fmaxf(hi, 0.0f));
        }
        __syncthreads();
    }
    {
        float bi = kv_blk_b[d];
        acc2[0] = acc2[1] = pk2(bi, bi);
        lin2<DD>(acc2, kv_blk_W + d, DD, h2);
        __syncthreads();
        #pragma unroll
        for (int p = 0; p < 2; p++) {
            float lo, hi; upk2(lo, hi, acc2[p]);
            h2[d][p] = pk2(lo, hi);
            if (path == 2) { kvs[2 * p][d] = lo; kvs[2 * p + 1][d] = hi; }
        }
        __syncthreads();
    }

    if (path == 1) {
        float bi = key_b[d];
        acc2[0] = acc2[1] = pk2(bi, bi);
        lin2<DD>(acc2, key_W + d, DD, h2);
        #pragma unroll
        for (int p = 0; p < 2; p++) {
            float lo, hi; upk2(lo, hi, acc2[p]);
            int b0 = 4 * bh + 2 * p;
            g_K[(b0 * RR + r) * DD + d] = lo;
            g_K[((b0 + 1) * RR + r) * DD + d] = hi;
        }
    } else {
        int w = d >> 5, lane = d & 31;
        float v = value_b[lane];
        const float* W = value_W + lane;
        #pragma unroll
        for (int base = 0; base < DD; base += 16) {
            float wb[16];
            #pragma unroll
            for (int u = 0; u < 16; u++) wb[u] = __ldg(W + (size_t)(base + u) * BDD);
            #pragma unroll
            for (int u = 0; u < 16; u++) v = fmaf(kvs[w][base + u], wb[u], v);
        }
        float ss = v * v;
        #pragma unroll
        for (int o = 16; o > 0; o >>= 1) ss += __shfl_xor_sync(0xffffffffu, ss, o);
        int b = 4 * bh + w;
        g_Vn[(b * RR + r) * BDD + lane] = v / fmaxf(sqrtf(ss), 1e-12f);
    }
}

// ---------------------------------------------------------------------------
// Kernel B: attention logits. One CTA per (s, 4 t's): packs q once, prefetches
// 4 K tiles in one prologue, then streams 4 W tiles back-to-back with no
// intermediate syncthreads (per-tile sred buffers). Amortizes CTA fixed cost.
// ---------------------------------------------------------------------------
__global__ __launch_bounds__(128) void kB(
    const float* __restrict__ qw, const float* __restrict__ qb)
{
    int t0 = blockIdx.x * TCH;
    int s = blockIdx.y;
    int tid = threadIdx.x;
    int w = tid >> 5, lane = tid & 31;
    int dbase = 4 * lane;

    __shared__ __align__(16) ull q2[DD][4];        // [d][pair]
    __shared__ __align__(16) ull k2[TCH][DD][4];   // [tt][d][pair]
    __shared__ float sred[TCH][4][BB];

    {   // prologue: pack q (once) + 4 K tiles
        int d = tid;
        float qv[BB];
        #pragma unroll
        for (int b = 0; b < BB; b++) qv[b] = g_q[(b * RR + s) * DD + d];
        #pragma unroll
        for (int p = 0; p < 4; p++) q2[d][p] = pk2(qv[2 * p], qv[2 * p + 1]);
        #pragma unroll
        for (int tt = 0; tt < TCH; tt++) {
            float kv[BB];
            #pragma unroll
            for (int b = 0; b < BB; b++) kv[b] = g_K[(b * RR + t0 + tt) * DD + d];
            #pragma unroll
            for (int p = 0; p < 4; p++) k2[tt][d][p] = pk2(kv[2 * p], kv[2 * p + 1]);
        }
    }
    __syncthreads();

    for (int tt = 0; tt < TCH; tt++) {
        int t = t0 + tt;
        ull acc2[4][4];
        #pragma unroll
        for (int c = 0; c < 4; c++)
            #pragma unroll
            for (int p = 0; p < 4; p++) acc2[c][p] = 0ull;

        const float* W = qw + ((size_t)(s * RR + t)) * DD * DD + (size_t)w * 32 * DD + dbase;
        #pragma unroll
        for (int ii0 = 0; ii0 < 32; ii0 += 8) {
            float4 wv[8];
            #pragma unroll
            for (int u = 0; u < 8; u++)
                wv[u] = __ldcs(reinterpret_cast<const float4*>(W + (size_t)(ii0 + u) * DD));
            #pragma unroll
            for (int u = 0; u < 8; u++) {
                int i = w * 32 + ii0 + u;
                ulonglong2 qA = *reinterpret_cast<const ulonglong2*>(&q2[i][0]);
                ulonglong2 qB = *reinterpret_cast<const ulonglong2*>(&q2[i][2]);
                ull w0 = pk2(wv[u].x, wv[u].x);
                ull w1 = pk2(wv[u].y, wv[u].y);
                ull w2_ = pk2(wv[u].z, wv[u].z);
                ull w3 = pk2(wv[u].w, wv[u].w);
                acc2[0][0] = fma2(qA.x, w0, acc2[0][0]);
                acc2[0][1] = fma2(qA.y, w0, acc2[0][1]);
                acc2[0][2] = fma2(qB.x, w0, acc2[0][2]);
                acc2[0][3] = fma2(qB.y, w0, acc2[0][3]);
                acc2[1][0] = fma2(qA.x, w1, acc2[1][0]);
                acc2[1][1] = fma2(qA.y, w1, acc2[1][1]);
                acc2[1][2] = fma2(qB.x, w1, acc2[1][2]);
                acc2[1][3] = fma2(qB.y, w1, acc2[1][3]);
                acc2[2][0] = fma2(qA.x, w2_, acc2[2][0]);
                acc2[2][1] = fma2(qA.y, w2_, acc2[2][1]);
                acc2[2][2] = fma2(qB.x, w2_, acc2[2][2]);
                acc2[2][3] = fma2(qB.y, w2_, acc2[2][3]);
                acc2[3][0] = fma2(qA.x, w3, acc2[3][0]);
                acc2[3][1] = fma2(qA.y, w3, acc2[3][1]);
                acc2[3][2] = fma2(qB.x, w3, acc2[3][2]);
                acc2[3][3] = fma2(qB.y, w3, acc2[3][3]);
            }
        }

        // tail: + bias (warp 0 only), dot with K, warp-reduce, stage to smem
        ull pp[4];
        #pragma unroll
        for (int p = 0; p < 4; p++) pp[p] = 0ull;
        float4 b4 = __ldcs(reinterpret_cast<const float4*>(
            qb + ((size_t)(s * RR + t)) * DD + dbase));
        float bias[4] = {b4.x, b4.y, b4.z, b4.w};
        #pragma unroll
        for (int c = 0; c < 4; c++) {
            int dd = dbase + c;
            #pragma unroll
            for (int p = 0; p < 4; p++) {
                ull a = acc2[c][p];
                if (w == 0) a = add2(a, pk2(bias[c], bias[c]));
                pp[p] = fma2(a, k2[tt][dd][p], pp[p]);
            }
        }
        float pf[BB];
        #pragma unroll
        for (int p = 0; p < 4; p++) upk2(pf[2 * p], pf[2 * p + 1], pp[p]);
        #pragma unroll
        for (int b = 0; b < BB; b++) {
            #pragma unroll
            for (int o = 16; o > 0; o >>= 1)
                pf[b] += __shfl_xor_sync(0xffffffffu, pf[b], o);
        }
        if (lane == 0) {
            #pragma unroll
            for (int b = 0; b < BB; b++) sred[tt][w][b] = pf[b];
        }
    }
    __syncthreads();
    if (tid < TCH * BB) {
        int tt = tid >> 3, b = tid & 7;
        float l = sred[tt][0][b] + sred[tt][1][b] + sred[tt][2][b] + sred[tt][3][b];
        g_attn[(b * RR + s) * RR + t0 + tt] = fmaxf(l, 0.0f);
    }
}

// ---------------------------------------------------------------------------
// Kernel C: normalize attn, attn@Vn, reproj, post block, out proj, denorm.
// ---------------------------------------------------------------------------
__global__ __launch_bounds__(128) void kC(
    const float* __restrict__ reproj_W, const float* __restrict__ reproj_b,
    const float* __restrict__ post_blk_W, const float* __restrict__ post_blk_b,
    const float* __restrict__ out_W, const float* __restrict__ out_b,
    const float* __restrict__ mean, const float* __restrict__ stddev,
    float* __restrict__ out)
{
    int s = blockIdx.x;
    int tid = threadIdx.x;

    __shared__ float at[BB][RR];
    __shared__ float ao[BB][BDD];
    __shared__ __align__(16) ull ar2[DD][4];
    __shared__ float hs[BB][DD];
    __shared__ float inv[BB];

    for (int idx = tid; idx < BB * RR; idx += 128) {
        int b = idx / RR, t = idx % RR;
        at[b][t] = g_attn[(b * RR + s) * RR + t];
    }
    __syncthreads();
    if (tid < BB) {
        float sum = 0.0f;
        #pragma unroll 10
        for (int t = 0; t < RR; t++) sum += at[tid][t];
        inv[tid] = 1.0f / (1e-8f + sum);
    }
    __syncthreads();

    {
        int bd = tid & 31;
        int bh = tid >> 5;
        int b0 = bh, b1 = bh + 4;
        float a0 = 0.0f, a1 = 0.0f;
        const float* V0 = g_Vn + (size_t)(b0 * RR) * BDD + bd;
        const float* V1 = g_Vn + (size_t)(b1 * RR) * BDD + bd;
        #pragma unroll 10
        for (int t = 0; t < RR; t++) {
            a0 = fmaf(at[b0][t], V0[(size_t)t * BDD], a0);
            a1 = fmaf(at[b1][t], V1[(size_t)t * BDD], a1);
        }
        ao[b0][bd] = a0 * inv[b0];
        ao[b1][bd] = a1 * inv[b1];
    }
    __syncthreads();

    int d = tid;
    {
        float rb = reproj_b[d];
        float acc[BB];
        #pragma unroll
        for (int b = 0; b < BB; b++) acc[b] = rb;
        const float* W = reproj_W + d;
        #pragma unroll
        for (int base = 0; base < BDD; base += 16) {
            float wb[16];
            #pragma unroll
            for (int u = 0; u < 16; u++) wb[u] = __ldg(W + (size_t)(base + u) * DD);
            #pragma unroll
            for (int u = 0; u < 16; u++)
                #pragma unroll
                for (int b = 0; b < BB; b++) acc[b] = fmaf(ao[b][base + u], wb[u], acc[b]);
        }
        #pragma unroll
        for (int p = 0; p < 4; p++)
            ar2[d][p] = pk2(fmaxf(acc[2 * p], 0.0f), fmaxf(acc[2 * p + 1], 0.0f));
        __syncthreads();
    }
    {
        float pb = post_blk_b[s * DD + d];
        ull acc2[4];
        #pragma unroll
        for (int p = 0; p < 4; p++) acc2[p] = pk2(pb, pb);
        const float* W = post_blk_W + (size_t)s * DD * DD + d;
        #pragma unroll
        for (int base = 0; base < DD; base += 16) {
            float wb[16];
            #pragma unroll
            for (int u = 0; u < 16; u++) wb[u] = __ldg(W + (size_t)(base + u) * DD);
            #pragma unroll
            for (int u = 0; u < 16; u++) {
                ull w2 = pk2(wb[u], wb[u]);
                ulonglong2 aA = *reinterpret_cast<const ulonglong2*>(&ar2[base + u][0]);
                ulonglong2 aB = *reinterpret_cast<const ulonglong2*>(&ar2[base + u][2]);
                acc2[0] = fma2(aA.x, w2, acc2[0]);
                acc2[1] = fma2(aA.y, w2, acc2[1]);
                acc2[2] = fma2(aB.x, w2, acc2[2]);
                acc2[3] = fma2(aB.y, w2, acc2[3]);
            }
        }
        #pragma unroll
        for (int p = 0; p < 4; p++) {
            float lo, hi; upk2(lo, hi, acc2[p]);
            hs[2 * p][d] = lo; hs[2 * p + 1][d] = hi;
        }
        __syncthreads();
    }
    {
        int b = tid >> 4, o = tid & 15;
        float p = out_b[s * OWW + o];
        const float* W = out_W + (size_t)s * DD * OWW + o;
        #pragma unroll
        for (int base = 0; base < DD; base += 16) {
            float wb[16];
            #pragma unroll
            for (int u = 0; u < 16; u++) wb[u] = __ldg(W + (size_t)(base + u) * OWW);
            #pragma unroll
            for (int u = 0; u < 16; u++) p = fmaf(hs[b][base + u], wb[u], p);
        }
        out[(b * RR + s) * OWW + o] = p * stddev[s] + mean[s];
    }
}

extern "C" void kernel_launch(void* const* d_in, const int* in_sizes, int n_in,
                              void* d_out, int out_size)
{
    const float* x          = (const float*)d_in[0];
    const float* mean       = (const float*)d_in[1];
    const float* stddev     = (const float*)d_in[2];
    const float* kv_in_W    = (const float*)d_in[3];
    const float* kv_in_b    = (const float*)d_in[4];
    const float* kv_blk_W   = (const float*)d_in[5];
    const float* kv_blk_b   = (const float*)d_in[6];
    const float* q_in_W     = (const float*)d_in[7];
    const float* q_in_b     = (const float*)d_in[8];
    const float* q_blk_W    = (const float*)d_in[9];
    const float* q_blk_b    = (const float*)d_in[10];
    const float* key_W      = (const float*)d_in[11];
    const float* key_b      = (const float*)d_in[12];
    const float* value_W    = (const float*)d_in[13];
    const float* value_b    = (const float*)d_in[14];
    const float* qw         = (const float*)d_in[15];
    const float* qb         = (const float*)d_in[16];
    const float* reproj_W   = (const float*)d_in[17];
    const float* reproj_b   = (const float*)d_in[18];
    const float* post_blk_W = (const float*)d_in[19];
    const float* post_blk_b = (const float*)d_in[20];
    const float* out_W      = (const float*)d_in[21];
    const float* out_b      = (const float*)d_in[22];
    float* out = (float*)d_out;

    kA<<<dim3(RR, 3, 2), 128>>>(x, mean, stddev, kv_in_W, kv_in_b, kv_blk_W, kv_blk_b,
                                q_in_W, q_in_b, q_blk_W, q_blk_b,
                                key_W, key_b, value_W, value_b);
    kB<<<dim3(RR / TCH, RR), 128>>>(qw, qb);
    kC<<<RR, 128>>>(reproj_W, reproj_b, post_blk_W, post_blk_b,
                    out_W, out_b, mean, stddev, out);
}